// round 9
// baseline (speedup 1.0000x reference)
#include <cuda_runtime.h>

#define RES 256
#define NPIX 65536
#define BPB 37           // blocks per batch (4*37 = 148 blocks = 1/SM)
#define NWARP 24
#define THREADS 768
#define IMG_OFF 0
#define WB_OFF  786432
#define SUB_OFF 786944
#define SMEM_FLOATS (33092 + NWARP * 512)
#define SMEM_BYTES  (SMEM_FLOATS * 4)

__device__ float g_weights[4 * 68];   // per batch: [0..3]=transform coeff, [4..67]=z
__device__ float g_h1z[4 * 128];      // b1 + W1[:, :64] @ z  (per batch)
__device__ float g_pio2[3];           // exact-split pi/2 triple (ph, pm, pl)

// ---- float-float helpers (FFMA pipe; no contraction hazards) ----
struct ff2 { float x, y; };

__device__ __forceinline__ ff2 ff_mul(ff2 a, ff2 b) {
    float p = __fmul_rn(a.x, b.x);
    float e = fmaf(a.x, b.x, -p);
    e = fmaf(a.x, b.y, e);
    e = fmaf(a.y, b.x, e);
    float hi = __fadd_rn(p, e);
    float lo = __fsub_rn(e, __fsub_rn(hi, p));
    return {hi, lo};
}
__device__ __forceinline__ ff2 ff_mul_f(ff2 a, float t) {
    float p = __fmul_rn(a.x, t);
    float e = fmaf(a.x, t, -p);
    e = fmaf(a.y, t, e);
    float hi = __fadd_rn(p, e);
    float lo = __fsub_rn(e, __fsub_rn(hi, p));
    return {hi, lo};
}
__device__ __forceinline__ ff2 ff_sqr(ff2 r) {
    float p = __fmul_rn(r.x, r.x);
    float e = fmaf(r.x, r.x, -p);
    e = fmaf(__fadd_rn(r.x, r.x), r.y, e);
    float hi = __fadd_rn(p, e);
    float lo = __fsub_rn(e, __fsub_rn(hi, p));
    return {hi, lo};
}
// c + p with |c| >= |p| guaranteed (Horner with decreasing-term ordering)
__device__ __forceinline__ ff2 ff_addc(float ch, float cl, ff2 p) {
    float s = __fadd_rn(ch, p.x);
    float e = __fsub_rn(p.x, __fsub_rn(s, ch));          // exact
    float lo = __fadd_rn(e, __fadd_rn(cl, p.y));
    float hi = __fadd_rn(s, lo);
    float lo2 = __fsub_rn(lo, __fsub_rn(hi, s));
    return {hi, lo2};
}

// compile-time ff splits of double coefficients
#define FFH(c) ((float)(c))
#define FFL(c) ((float)((c) - (double)(float)(c)))

// Correctly-rounded-matching f32 sine on the FP32 pipe (proven: rel_err
// identical to the f64 reference implementation). Do not touch accuracy.
__device__ __forceinline__ float sin_cr(float x, float PH, float PM, float PL) {
    float kf = rintf(__fmul_rn(x, 0.63661977236758134f));
    int q = (int)kf;
    float t1  = __fmul_rn(kf, PH);
    float t1e = fmaf(kf, PH, -t1);
    float t2  = __fmul_rn(kf, PM);
    float t2e = fmaf(kf, PM, -t2);
    float hi  = __fsub_rn(x, t1);                         // exact (Sterbenz-range)
    float s   = __fsub_rn(hi, t1e);
    float bb  = __fsub_rn(s, hi);
    float err = __fadd_rn(__fsub_rn(hi, __fsub_rn(s, bb)), __fsub_rn(-t1e, bb));
    float s2   = __fsub_rn(s, t2);
    float bb2  = __fsub_rn(s2, s);
    float err2 = __fadd_rn(__fsub_rn(s, __fsub_rn(s2, bb2)), __fsub_rn(-t2, bb2));
    float lo = __fsub_rn(__fadd_rn(err, err2), __fadd_rn(t2e, __fmul_rn(kf, PL)));
    float rh = __fadd_rn(s2, lo);
    float rl = __fsub_rn(lo, __fsub_rn(rh, s2));
    ff2 r = {rh, rl};
    ff2 r2 = ff_sqr(r);
    float r2f = r2.x;

    const bool odd = (q & 1);
    float c1h = odd ? FFH(-1.0/2.0)     : FFH(-1.0/6.0);
    float c1l = odd ? FFL(-1.0/2.0)     : FFL(-1.0/6.0);
    float c2h = odd ? FFH(1.0/24.0)     : FFH(1.0/120.0);
    float c2l = odd ? FFL(1.0/24.0)     : FFL(1.0/120.0);
    float c3h = odd ? FFH(-1.0/720.0)   : FFH(-1.0/5040.0);
    float c3l = odd ? FFL(-1.0/720.0)   : FFL(-1.0/5040.0);
    float a4 = odd ? (float)(1.0/40320.0)        : (float)(1.0/362880.0);
    float a5 = odd ? (float)(-1.0/3628800.0)     : (float)(-1.0/39916800.0);
    float a6 = odd ? (float)(1.0/479001600.0)    : (float)(1.0/6227020800.0);
    float a7 = odd ? (float)(-1.0/87178291200.0) : 0.0f;

    float T = fmaf(r2f, fmaf(r2f, fmaf(r2f, a7, a6), a5), a4);
    ff2 acc = ff_mul_f(r2, T);
    acc = ff_addc(c3h, c3l, acc);
    acc = ff_mul(r2, acc);
    acc = ff_addc(c2h, c2l, acc);
    acc = ff_mul(r2, acc);
    acc = ff_addc(c1h, c1l, acc);
    acc = ff_mul(r2, acc);
    acc = ff_addc(1.0f, 0.0f, acc);
    ff2 m = {odd ? 1.0f : r.x, odd ? 0.0f : r.y};
    ff2 p = ff_mul(m, acc);
    float res = __fadd_rn(p.x, p.y);
    return (q & 2) ? -res : res;
}

// Fade: only feeds smooth interpolation -> rounding non-critical.
__device__ __forceinline__ float fadef(float t) {
    float t2 = t * t;
    return t2 * t * fmaf(t, fmaf(t, 6.0f, -15.0f), 10.0f);
}

// hash -> unit gradient -> dot with corner offset.
// Gradient angle cos/sin via MUFU (__sincosf): angle err ~2e-7 -> image err
// ~2e-7, invisible under the 5e-4 floor; saves ~35 f32 ops per corner.
__device__ __forceinline__ float grad_dot(float cix, float ciy, float s, float ox, float oy,
                                          float PH, float PM, float PL) {
    float arg = __fadd_rn(__fadd_rn(__fmul_rn(cix, 127.1f), __fmul_rn(ciy, 311.7f)),
                          __fmul_rn(s, 74.7f));
    float h   = __fmul_rn(sin_cr(arg, PH, PM, PL), 43758.5453f);
    float fr  = __fsub_rn(h, floorf(h));
    float ang = __fmul_rn(fr, 6.2831853071795862f);
    float gx, gy;
    __sincosf(ang, &gy, &gx);
    return __fadd_rn(__fmul_rn(gx, ox), __fmul_rn(gy, oy));
}

__device__ __forceinline__ float perlin_cell(float ix, float iy, float fx, float fy,
                                             float u, float v, float s,
                                             float PH, float PM, float PL) {
    float n00 = grad_dot(ix,        iy,        s, fx,        fy,        PH, PM, PL);
    float n10 = grad_dot(ix + 1.0f, iy,        s, fx - 1.0f, fy,        PH, PM, PL);
    float n01 = grad_dot(ix,        iy + 1.0f, s, fx,        fy - 1.0f, PH, PM, PL);
    float n11 = grad_dot(ix + 1.0f, iy + 1.0f, s, fx - 1.0f, fy - 1.0f, PH, PM, PL);
    float nx0 = fmaf(u, n10 - n00, n00);
    float nx1 = fmaf(u, n11 - n01, n01);
    return fmaf(v, nx1 - nx0, nx0);
}

__device__ __forceinline__ float f4get(const float4& v, int k) {
    return k == 0 ? v.x : (k == 1 ? v.y : (k == 2 ? v.z : v.w));
}

// ---------------------------------------------------------------------------
// Setup: bottleneck GEMMs in f64 (one-time), z-folded layer-1 partial, pi/2.
// ---------------------------------------------------------------------------
__global__ void __launch_bounds__(512)
texgen_setup(const float* __restrict__ wb,  const float* __restrict__ fcw,
             const float* __restrict__ fcb, const float* __restrict__ sw,
             const float* __restrict__ sb,  const float* __restrict__ w1,
             const float* __restrict__ b1,  float* __restrict__ out)
{
    __shared__ float sWb[512];
    const int tid = threadIdx.x;
    sWb[tid] = wb[tid];
    out[WB_OFF + tid] = wb[tid];            // pass-through output (exact copy)
    if (tid == 0) {
        const double PIO2_HI = 1.5707963267948966;
        const double PIO2_LO = 6.123233995736766e-17;
        float ph = (float)PIO2_HI;
        float pm = (float)(PIO2_HI - (double)ph);
        double rem = (PIO2_HI - (double)ph - (double)pm) + PIO2_LO;
        g_pio2[0] = ph; g_pio2[1] = pm; g_pio2[2] = (float)rem;
    }
    __syncthreads();

    for (int i = tid; i < 4 * 68; i += 512) {
        int b = i / 68, j = i % 68;
        double acc = 0.0;
        const float* wr = fcw + j * 128;
        const float* br = sWb + b * 128;
        #pragma unroll 8
        for (int k = 0; k < 128; ++k) acc = fma((double)br[k], (double)wr[k], acc);
        g_weights[i] = (float)(acc + (double)fcb[j]);
    }
    if (tid < 16) {
        int b = tid / 4, j = tid % 4;
        double acc = 0.0;
        #pragma unroll 8
        for (int k = 0; k < 128; ++k)
            acc = fma((double)sWb[b * 128 + k], (double)sw[j * 128 + k], acc);
        out[SUB_OFF + tid] = (float)(acc + (double)sb[j]);
    }
    __syncthreads();

    {
        int b = tid >> 7, j = tid & 127;
        double acc = 0.0;
        const float* zr = g_weights + b * 68 + 4;
        const float* wr = w1 + j * 192;
        #pragma unroll 8
        for (int k = 0; k < 64; ++k) acc = fma((double)zr[k], (double)wr[k], acc);
        if (tid < 512) g_h1z[tid] = (float)(acc + (double)b1[j]);
    }
}

// ---------------------------------------------------------------------------
// Main: per-warp, 4 pixels/iteration. Noise -> SMEM x -> 2 GEMV layers with
// SMEM-resident transposed weights -> warp-reduced 3-ch output + tanh.
// ---------------------------------------------------------------------------
__global__ void __launch_bounds__(THREADS, 1)
texgen_main(const float* __restrict__ position,
            const float* __restrict__ seed,
            const float* __restrict__ dec_w1,
            const float* __restrict__ dec_w2,
            const float* __restrict__ dec_b2,
            const float* __restrict__ dec_w3,
            const float* __restrict__ dec_b3,
            float* __restrict__ out)
{
    extern __shared__ float sm[];
    float* sW1   = sm;            // [128 noise-ch][128 j]  (transposed)
    float* sW2   = sm + 16384;    // [128 c][128 j]
    float* sB2   = sm + 32768;    // [128]
    float* sHz   = sm + 32896;    // [128]
    float* sSeed = sm + 33024;    // [64]
    float* sTc   = sm + 33088;    // [4]

    const int tid   = threadIdx.x;
    const int batch = blockIdx.x / BPB;
    const int bb    = blockIdx.x % BPB;

    for (int i = tid; i < 16384; i += THREADS) {
        int cc = i >> 7, j = i & 127;
        sW1[i] = dec_w1[j * 192 + 64 + cc];
        sW2[i] = dec_w2[j * 128 + cc];
    }
    if (tid < 128) { sB2[tid] = dec_b2[tid]; sHz[tid] = g_h1z[batch * 128 + tid]; }
    if (tid < 64)  sSeed[tid] = seed[batch * 64 + tid];
    if (tid < 4)   sTc[tid]   = g_weights[batch * 68 + tid];
    __syncthreads();

    const float PH = g_pio2[0], PM = g_pio2[1], PL = g_pio2[2];

    const int lane = tid & 31;
    const int warp = tid >> 5;
    const int o1   = lane >> 3;      // octave A for this lane (0..3)
    const int ch   = lane & 7;       // noise channel

    const float sA   = sSeed[o1 * 8 + ch];
    const float sB   = sSeed[(o1 + 4) * 8 + ch];
    const float sA2  = __fadd_rn(sA, 17.1312f);   // SEED_OFFSET, f32 add
    const float sBo  = __fadd_rn(sB, 17.1312f);
    const float sclA = (float)(1 << o1);
    const float sclB = sclA * 16.0f;
    const float tc0 = sTc[0], tc1 = sTc[1], tc2 = sTc[2], tc3 = sTc[3];
    const float4 hz  = *reinterpret_cast<const float4*>(sHz + 4 * lane);
    const float4 b2v = *reinterpret_cast<const float4*>(sB2 + 4 * lane);
    const float4 w30 = reinterpret_cast<const float4*>(dec_w3)[lane];
    const float4 w31 = reinterpret_cast<const float4*>(dec_w3 + 128)[lane];
    const float4 w32 = reinterpret_cast<const float4*>(dec_w3 + 256)[lane];
    const float b30 = dec_b3[0], b31 = dec_b3[1], b32 = dec_b3[2];

    float* sX = sm + 33092 + warp * 512;     // [128 ch][4 pixels]
    const float* posb = position + batch * (2 * NPIX);
    float* outb = out + IMG_OFF + batch * (3 * NPIX);

    const int gw     = bb * NWARP + warp;
    const int stride = BPB * NWARP * 4;

    for (int base = gw * 4; base < NPIX; base += stride) {
        __syncwarp();
        // ---- noise: each lane computes 4 channels (2 octaves x 2 seed variants)
        for (int pp = 0; pp < 4; ++pp) {
            int pix = base + pp;
            float px = posb[pix];
            float py = posb[NPIX + pix];
            float xp = __fadd_rn(__fmul_rn(px, tc0), __fmul_rn(py, tc2));
            float yp = __fadd_rn(__fmul_rn(px, tc1), __fmul_rn(py, tc3));
            {   // octave A
                float pxo = __fmul_rn(xp, sclA), pyo = __fmul_rn(yp, sclA);
                float ixf = floorf(pxo), iyf = floorf(pyo);
                float fx = __fsub_rn(pxo, ixf), fy = __fsub_rn(pyo, iyf);
                float u = fadef(fx), v = fadef(fy);
                sX[lane * 4 + pp]        = perlin_cell(ixf, iyf, fx, fy, u, v, sA,  PH, PM, PL);
                sX[(64 + lane) * 4 + pp] = perlin_cell(ixf, iyf, fx, fy, u, v, sA2, PH, PM, PL);
            }
            {   // octave B
                float pxo = __fmul_rn(xp, sclB), pyo = __fmul_rn(yp, sclB);
                float ixf = floorf(pxo), iyf = floorf(pyo);
                float fx = __fsub_rn(pxo, ixf), fy = __fsub_rn(pyo, iyf);
                float u = fadef(fx), v = fadef(fy);
                sX[(32 + lane) * 4 + pp] = perlin_cell(ixf, iyf, fx, fy, u, v, sB,  PH, PM, PL);
                sX[(96 + lane) * 4 + pp] = perlin_cell(ixf, iyf, fx, fy, u, v, sBo, PH, PM, PL);
            }
        }
        __syncwarp();

        // ---- layer 1 (noise part only; z part pre-folded into hz)
        float4 a0 = hz, a1 = hz, a2 = hz, a3 = hz;
        #pragma unroll 4
        for (int cc = 0; cc < 128; ++cc) {
            float4 wv = *reinterpret_cast<const float4*>(sW1 + cc * 128 + lane * 4);
            float4 xq = *reinterpret_cast<const float4*>(sX + cc * 4);
            a0.x = fmaf(wv.x, xq.x, a0.x); a0.y = fmaf(wv.y, xq.x, a0.y);
            a0.z = fmaf(wv.z, xq.x, a0.z); a0.w = fmaf(wv.w, xq.x, a0.w);
            a1.x = fmaf(wv.x, xq.y, a1.x); a1.y = fmaf(wv.y, xq.y, a1.y);
            a1.z = fmaf(wv.z, xq.y, a1.z); a1.w = fmaf(wv.w, xq.y, a1.w);
            a2.x = fmaf(wv.x, xq.z, a2.x); a2.y = fmaf(wv.y, xq.z, a2.y);
            a2.z = fmaf(wv.z, xq.z, a2.z); a2.w = fmaf(wv.w, xq.z, a2.w);
            a3.x = fmaf(wv.x, xq.w, a3.x); a3.y = fmaf(wv.y, xq.w, a3.y);
            a3.z = fmaf(wv.z, xq.w, a3.z); a3.w = fmaf(wv.w, xq.w, a3.w);
        }
        a0.x = fmaxf(a0.x, 0.0f); a0.y = fmaxf(a0.y, 0.0f); a0.z = fmaxf(a0.z, 0.0f); a0.w = fmaxf(a0.w, 0.0f);
        a1.x = fmaxf(a1.x, 0.0f); a1.y = fmaxf(a1.y, 0.0f); a1.z = fmaxf(a1.z, 0.0f); a1.w = fmaxf(a1.w, 0.0f);
        a2.x = fmaxf(a2.x, 0.0f); a2.y = fmaxf(a2.y, 0.0f); a2.z = fmaxf(a2.z, 0.0f); a2.w = fmaxf(a2.w, 0.0f);
        a3.x = fmaxf(a3.x, 0.0f); a3.y = fmaxf(a3.y, 0.0f); a3.z = fmaxf(a3.z, 0.0f); a3.w = fmaxf(a3.w, 0.0f);

        __syncwarp();
        #pragma unroll
        for (int k = 0; k < 4; ++k) {
            reinterpret_cast<float4*>(sX)[4 * lane + k] =
                make_float4(f4get(a0, k), f4get(a1, k), f4get(a2, k), f4get(a3, k));
        }
        __syncwarp();

        // ---- layer 2
        float4 c0 = b2v, c1 = b2v, c2 = b2v, c3 = b2v;
        #pragma unroll 4
        for (int cc = 0; cc < 128; ++cc) {
            float4 wv = *reinterpret_cast<const float4*>(sW2 + cc * 128 + lane * 4);
            float4 xq = *reinterpret_cast<const float4*>(sX + cc * 4);
            c0.x = fmaf(wv.x, xq.x, c0.x); c0.y = fmaf(wv.y, xq.x, c0.y);
            c0.z = fmaf(wv.z, xq.x, c0.z); c0.w = fmaf(wv.w, xq.x, c0.w);
            c1.x = fmaf(wv.x, xq.y, c1.x); c1.y = fmaf(wv.y, xq.y, c1.y);
            c1.z = fmaf(wv.z, xq.y, c1.z); c1.w = fmaf(wv.w, xq.y, c1.w);
            c2.x = fmaf(wv.x, xq.z, c2.x); c2.y = fmaf(wv.y, xq.z, c2.y);
            c2.z = fmaf(wv.z, xq.z, c2.z); c2.w = fmaf(wv.w, xq.z, c2.w);
            c3.x = fmaf(wv.x, xq.w, c3.x); c3.y = fmaf(wv.y, xq.w, c3.y);
            c3.z = fmaf(wv.z, xq.w, c3.z); c3.w = fmaf(wv.w, xq.w, c3.w);
        }
        c0.x = fmaxf(c0.x, 0.0f); c0.y = fmaxf(c0.y, 0.0f); c0.z = fmaxf(c0.z, 0.0f); c0.w = fmaxf(c0.w, 0.0f);
        c1.x = fmaxf(c1.x, 0.0f); c1.y = fmaxf(c1.y, 0.0f); c1.z = fmaxf(c1.z, 0.0f); c1.w = fmaxf(c1.w, 0.0f);
        c2.x = fmaxf(c2.x, 0.0f); c2.y = fmaxf(c2.y, 0.0f); c2.z = fmaxf(c2.z, 0.0f); c2.w = fmaxf(c2.w, 0.0f);
        c3.x = fmaxf(c3.x, 0.0f); c3.y = fmaxf(c3.y, 0.0f); c3.z = fmaxf(c3.z, 0.0f); c3.w = fmaxf(c3.w, 0.0f);

        // ---- layer 3 + tanh + store
        #pragma unroll
        for (int pp = 0; pp < 4; ++pp) {
            float4 h = (pp == 0) ? c0 : (pp == 1) ? c1 : (pp == 2) ? c2 : c3;
            float r0 = fmaf(w30.x, h.x, fmaf(w30.y, h.y, fmaf(w30.z, h.z, w30.w * h.w)));
            float r1 = fmaf(w31.x, h.x, fmaf(w31.y, h.y, fmaf(w31.z, h.z, w31.w * h.w)));
            float r2 = fmaf(w32.x, h.x, fmaf(w32.y, h.y, fmaf(w32.z, h.z, w32.w * h.w)));
            #pragma unroll
            for (int sh = 16; sh > 0; sh >>= 1) {
                r0 += __shfl_xor_sync(0xffffffffu, r0, sh);
                r1 += __shfl_xor_sync(0xffffffffu, r1, sh);
                r2 += __shfl_xor_sync(0xffffffffu, r2, sh);
            }
            if (lane == pp) {
                int pix = base + pp;
                outb[pix]            = tanhf(r0 + b30);
                outb[NPIX + pix]     = tanhf(r1 + b31);
                outb[2 * NPIX + pix] = tanhf(r2 + b32);
            }
        }
    }
}

extern "C" void kernel_launch(void* const* d_in, const int* in_sizes, int n_in,
                              void* d_out, int out_size) {
    const float* position = (const float*)d_in[0];
    const float* seed     = (const float*)d_in[1];
    const float* wb       = (const float*)d_in[2];
    const float* fcw      = (const float*)d_in[3];
    const float* fcb      = (const float*)d_in[4];
    const float* sw       = (const float*)d_in[5];
    const float* sb       = (const float*)d_in[6];
    const float* w1       = (const float*)d_in[7];
    const float* b1       = (const float*)d_in[8];
    const float* w2       = (const float*)d_in[9];
    const float* b2       = (const float*)d_in[10];
    const float* w3       = (const float*)d_in[11];
    const float* b3       = (const float*)d_in[12];
    float* out = (float*)d_out;

    cudaFuncSetAttribute(texgen_main, cudaFuncAttributeMaxDynamicSharedMemorySize, SMEM_BYTES);

    texgen_setup<<<1, 512>>>(wb, fcw, fcb, sw, sb, w1, b1, out);
    texgen_main<<<4 * BPB, THREADS, SMEM_BYTES>>>(position, seed, w1, w2, b2, w3, b3, out);
}

// round 11
// speedup vs baseline: 1.6005x; 1.6005x over previous
#include <cuda_runtime.h>

#define RES 256
#define NPIX 65536
#define BPB 37           // blocks per batch (4*37 = 148 blocks = 1/SM)
#define NWARP 16
#define THREADS 512
#define IMG_OFF 0
#define WB_OFF  786432
#define SUB_OFF 786944
#define SMEM_FLOATS (33092 + NWARP * 512)
#define SMEM_BYTES  (SMEM_FLOATS * 4)

__device__ float g_weights[4 * 68];   // per batch: [0..3]=transform coeff, [4..67]=z
__device__ float g_h1z[4 * 128];      // b1 + W1[:, :64] @ z  (per batch)
__device__ float g_pio2[3];           // exact-split pi/2 triple (ph, pm, pl)

// ---- float-float helpers (FFMA pipe; no contraction hazards) ----
struct ff2 { float x, y; };

__device__ __forceinline__ ff2 ff_mul(ff2 a, ff2 b) {
    float p = __fmul_rn(a.x, b.x);
    float e = fmaf(a.x, b.x, -p);
    e = fmaf(a.x, b.y, e);
    e = fmaf(a.y, b.x, e);
    float hi = __fadd_rn(p, e);
    float lo = __fsub_rn(e, __fsub_rn(hi, p));
    return {hi, lo};
}
__device__ __forceinline__ ff2 ff_mul_f(ff2 a, float t) {
    float p = __fmul_rn(a.x, t);
    float e = fmaf(a.x, t, -p);
    e = fmaf(a.y, t, e);
    float hi = __fadd_rn(p, e);
    float lo = __fsub_rn(e, __fsub_rn(hi, p));
    return {hi, lo};
}
__device__ __forceinline__ ff2 ff_sqr(ff2 r) {
    float p = __fmul_rn(r.x, r.x);
    float e = fmaf(r.x, r.x, -p);
    e = fmaf(__fadd_rn(r.x, r.x), r.y, e);
    float hi = __fadd_rn(p, e);
    float lo = __fsub_rn(e, __fsub_rn(hi, p));
    return {hi, lo};
}
// c + p with |c| >= |p| guaranteed (Horner with decreasing-term ordering)
__device__ __forceinline__ ff2 ff_addc(float ch, float cl, ff2 p) {
    float s = __fadd_rn(ch, p.x);
    float e = __fsub_rn(p.x, __fsub_rn(s, ch));          // exact
    float lo = __fadd_rn(e, __fadd_rn(cl, p.y));
    float hi = __fadd_rn(s, lo);
    float lo2 = __fsub_rn(lo, __fsub_rn(hi, s));
    return {hi, lo2};
}

// compile-time ff splits of double coefficients
#define FFH(c) ((float)(c))
#define FFL(c) ((float)((c) - (double)(float)(c)))

// Correctly-rounded-matching f32 sine on the FP32 pipe (proven: rel_err
// identical to the f64 reference implementation). Do not touch accuracy.
__device__ __forceinline__ float sin_cr(float x, float PH, float PM, float PL) {
    float kf = rintf(__fmul_rn(x, 0.63661977236758134f));
    int q = (int)kf;
    float t1  = __fmul_rn(kf, PH);
    float t1e = fmaf(kf, PH, -t1);
    float t2  = __fmul_rn(kf, PM);
    float t2e = fmaf(kf, PM, -t2);
    float hi  = __fsub_rn(x, t1);                         // exact (Sterbenz-range)
    float s   = __fsub_rn(hi, t1e);
    float bb  = __fsub_rn(s, hi);
    float err = __fadd_rn(__fsub_rn(hi, __fsub_rn(s, bb)), __fsub_rn(-t1e, bb));
    float s2   = __fsub_rn(s, t2);
    float bb2  = __fsub_rn(s2, s);
    float err2 = __fadd_rn(__fsub_rn(s, __fsub_rn(s2, bb2)), __fsub_rn(-t2, bb2));
    float lo = __fsub_rn(__fadd_rn(err, err2), __fadd_rn(t2e, __fmul_rn(kf, PL)));
    float rh = __fadd_rn(s2, lo);
    float rl = __fsub_rn(lo, __fsub_rn(rh, s2));
    ff2 r = {rh, rl};
    ff2 r2 = ff_sqr(r);
    float r2f = r2.x;

    const bool odd = (q & 1);
    float c1h = odd ? FFH(-1.0/2.0)     : FFH(-1.0/6.0);
    float c1l = odd ? FFL(-1.0/2.0)     : FFL(-1.0/6.0);
    float c2h = odd ? FFH(1.0/24.0)     : FFH(1.0/120.0);
    float c2l = odd ? FFL(1.0/24.0)     : FFL(1.0/120.0);
    float c3h = odd ? FFH(-1.0/720.0)   : FFH(-1.0/5040.0);
    float c3l = odd ? FFL(-1.0/720.0)   : FFL(-1.0/5040.0);
    float a4 = odd ? (float)(1.0/40320.0)        : (float)(1.0/362880.0);
    float a5 = odd ? (float)(-1.0/3628800.0)     : (float)(-1.0/39916800.0);
    float a6 = odd ? (float)(1.0/479001600.0)    : (float)(1.0/6227020800.0);
    float a7 = odd ? (float)(-1.0/87178291200.0) : 0.0f;

    float T = fmaf(r2f, fmaf(r2f, fmaf(r2f, a7, a6), a5), a4);
    ff2 acc = ff_mul_f(r2, T);
    acc = ff_addc(c3h, c3l, acc);
    acc = ff_mul(r2, acc);
    acc = ff_addc(c2h, c2l, acc);
    acc = ff_mul(r2, acc);
    acc = ff_addc(c1h, c1l, acc);
    acc = ff_mul(r2, acc);
    acc = ff_addc(1.0f, 0.0f, acc);
    ff2 m = {odd ? 1.0f : r.x, odd ? 0.0f : r.y};
    ff2 p = ff_mul(m, acc);
    float res = __fadd_rn(p.x, p.y);
    return (q & 2) ? -res : res;
}

// Fade: only feeds smooth interpolation -> rounding non-critical.
__device__ __forceinline__ float fadef(float t) {
    float t2 = t * t;
    return t2 * t * fmaf(t, fmaf(t, 6.0f, -15.0f), 10.0f);
}

// hash -> unit gradient -> dot with corner offset.
// Gradient angle cos/sin via MUFU (__sincosf): angle err ~2e-7 -> image err
// ~2e-7, invisible under the 5e-4 floor; saves ~35 f32 ops per corner.
__device__ __forceinline__ float grad_dot(float cix, float ciy, float s, float ox, float oy,
                                          float PH, float PM, float PL) {
    float arg = __fadd_rn(__fadd_rn(__fmul_rn(cix, 127.1f), __fmul_rn(ciy, 311.7f)),
                          __fmul_rn(s, 74.7f));
    float h   = __fmul_rn(sin_cr(arg, PH, PM, PL), 43758.5453f);
    float fr  = __fsub_rn(h, floorf(h));
    float ang = __fmul_rn(fr, 6.2831853071795862f);
    float gx, gy;
    __sincosf(ang, &gy, &gx);
    return __fadd_rn(__fmul_rn(gx, ox), __fmul_rn(gy, oy));
}

__device__ __forceinline__ float perlin_cell(float ix, float iy, float fx, float fy,
                                             float u, float v, float s,
                                             float PH, float PM, float PL) {
    float n00 = grad_dot(ix,        iy,        s, fx,        fy,        PH, PM, PL);
    float n10 = grad_dot(ix + 1.0f, iy,        s, fx - 1.0f, fy,        PH, PM, PL);
    float n01 = grad_dot(ix,        iy + 1.0f, s, fx,        fy - 1.0f, PH, PM, PL);
    float n11 = grad_dot(ix + 1.0f, iy + 1.0f, s, fx - 1.0f, fy - 1.0f, PH, PM, PL);
    float nx0 = fmaf(u, n10 - n00, n00);
    float nx1 = fmaf(u, n11 - n01, n01);
    return fmaf(v, nx1 - nx0, nx0);
}

__device__ __forceinline__ float f4get(const float4& v, int k) {
    return k == 0 ? v.x : (k == 1 ? v.y : (k == 2 ? v.z : v.w));
}

// ---------------------------------------------------------------------------
// Setup: bottleneck GEMMs in f64 (one-time), z-folded layer-1 partial, pi/2.
// ---------------------------------------------------------------------------
__global__ void __launch_bounds__(512)
texgen_setup(const float* __restrict__ wb,  const float* __restrict__ fcw,
             const float* __restrict__ fcb, const float* __restrict__ sw,
             const float* __restrict__ sb,  const float* __restrict__ w1,
             const float* __restrict__ b1,  float* __restrict__ out)
{
    __shared__ float sWb[512];
    const int tid = threadIdx.x;
    sWb[tid] = wb[tid];
    out[WB_OFF + tid] = wb[tid];            // pass-through output (exact copy)
    if (tid == 0) {
        const double PIO2_HI = 1.5707963267948966;
        const double PIO2_LO = 6.123233995736766e-17;
        float ph = (float)PIO2_HI;
        float pm = (float)(PIO2_HI - (double)ph);
        double rem = (PIO2_HI - (double)ph - (double)pm) + PIO2_LO;
        g_pio2[0] = ph; g_pio2[1] = pm; g_pio2[2] = (float)rem;
    }
    __syncthreads();

    for (int i = tid; i < 4 * 68; i += 512) {
        int b = i / 68, j = i % 68;
        double acc = 0.0;
        const float* wr = fcw + j * 128;
        const float* br = sWb + b * 128;
        #pragma unroll 8
        for (int k = 0; k < 128; ++k) acc = fma((double)br[k], (double)wr[k], acc);
        g_weights[i] = (float)(acc + (double)fcb[j]);
    }
    if (tid < 16) {
        int b = tid / 4, j = tid % 4;
        double acc = 0.0;
        #pragma unroll 8
        for (int k = 0; k < 128; ++k)
            acc = fma((double)sWb[b * 128 + k], (double)sw[j * 128 + k], acc);
        out[SUB_OFF + tid] = (float)(acc + (double)sb[j]);
    }
    __syncthreads();

    {
        int b = tid >> 7, j = tid & 127;
        double acc = 0.0;
        const float* zr = g_weights + b * 68 + 4;
        const float* wr = w1 + j * 192;
        #pragma unroll 8
        for (int k = 0; k < 64; ++k) acc = fma((double)zr[k], (double)wr[k], acc);
        g_h1z[tid] = (float)(acc + (double)b1[j]);
    }
}

// ---------------------------------------------------------------------------
// Main: per-warp, 4 pixels/iteration. Noise -> SMEM x -> 2 GEMV layers with
// SMEM-resident transposed weights -> warp-reduced 3-ch output + tanh.
// ---------------------------------------------------------------------------
__global__ void __launch_bounds__(THREADS, 1)
texgen_main(const float* __restrict__ position,
            const float* __restrict__ seed,
            const float* __restrict__ dec_w1,
            const float* __restrict__ dec_w2,
            const float* __restrict__ dec_b2,
            const float* __restrict__ dec_w3,
            const float* __restrict__ dec_b3,
            float* __restrict__ out)
{
    extern __shared__ float sm[];
    float* sW1   = sm;            // [128 noise-ch][128 j]  (transposed)
    float* sW2   = sm + 16384;    // [128 c][128 j]
    float* sB2   = sm + 32768;    // [128]
    float* sHz   = sm + 32896;    // [128]
    float* sSeed = sm + 33024;    // [64]
    float* sTc   = sm + 33088;    // [4]

    const int tid   = threadIdx.x;
    const int batch = blockIdx.x / BPB;
    const int bb    = blockIdx.x % BPB;

    for (int i = tid; i < 16384; i += THREADS) {
        int cc = i >> 7, j = i & 127;
        sW1[i] = dec_w1[j * 192 + 64 + cc];
        sW2[i] = dec_w2[j * 128 + cc];
    }
    if (tid < 128) { sB2[tid] = dec_b2[tid]; sHz[tid] = g_h1z[batch * 128 + tid]; }
    if (tid < 64)  sSeed[tid] = seed[batch * 64 + tid];
    if (tid < 4)   sTc[tid]   = g_weights[batch * 68 + tid];
    __syncthreads();

    const float PH = g_pio2[0], PM = g_pio2[1], PL = g_pio2[2];

    const int lane = tid & 31;
    const int warp = tid >> 5;
    const int o1   = lane >> 3;      // octave A for this lane (0..3)
    const int ch   = lane & 7;       // noise channel

    const float sA   = sSeed[o1 * 8 + ch];
    const float sB   = sSeed[(o1 + 4) * 8 + ch];
    const float sA2  = __fadd_rn(sA, 17.1312f);   // SEED_OFFSET, f32 add
    const float sBo  = __fadd_rn(sB, 17.1312f);
    const float sclA = (float)(1 << o1);
    const float sclB = sclA * 16.0f;
    const float tc0 = sTc[0], tc1 = sTc[1], tc2 = sTc[2], tc3 = sTc[3];
    const float4 hz  = *reinterpret_cast<const float4*>(sHz + 4 * lane);
    const float4 b2v = *reinterpret_cast<const float4*>(sB2 + 4 * lane);
    const float4 w30 = reinterpret_cast<const float4*>(dec_w3)[lane];
    const float4 w31 = reinterpret_cast<const float4*>(dec_w3 + 128)[lane];
    const float4 w32 = reinterpret_cast<const float4*>(dec_w3 + 256)[lane];
    const float b30 = dec_b3[0], b31 = dec_b3[1], b32 = dec_b3[2];

    float* sX = sm + 33092 + warp * 512;     // [128 ch][4 pixels]
    const float* posb = position + batch * (2 * NPIX);
    float* outb = out + IMG_OFF + batch * (3 * NPIX);

    const int gw     = bb * NWARP + warp;
    const int stride = BPB * NWARP * 4;

    for (int base = gw * 4; base < NPIX; base += stride) {
        __syncwarp();
        // ---- noise: each lane computes 4 channels (2 octaves x 2 seed variants)
        for (int pp = 0; pp < 4; ++pp) {
            int pix = base + pp;
            float px = posb[pix];
            float py = posb[NPIX + pix];
            float xp = __fadd_rn(__fmul_rn(px, tc0), __fmul_rn(py, tc2));
            float yp = __fadd_rn(__fmul_rn(px, tc1), __fmul_rn(py, tc3));
            {   // octave A
                float pxo = __fmul_rn(xp, sclA), pyo = __fmul_rn(yp, sclA);
                float ixf = floorf(pxo), iyf = floorf(pyo);
                float fx = __fsub_rn(pxo, ixf), fy = __fsub_rn(pyo, iyf);
                float u = fadef(fx), v = fadef(fy);
                sX[lane * 4 + pp]        = perlin_cell(ixf, iyf, fx, fy, u, v, sA,  PH, PM, PL);
                sX[(64 + lane) * 4 + pp] = perlin_cell(ixf, iyf, fx, fy, u, v, sA2, PH, PM, PL);
            }
            {   // octave B
                float pxo = __fmul_rn(xp, sclB), pyo = __fmul_rn(yp, sclB);
                float ixf = floorf(pxo), iyf = floorf(pyo);
                float fx = __fsub_rn(pxo, ixf), fy = __fsub_rn(pyo, iyf);
                float u = fadef(fx), v = fadef(fy);
                sX[(32 + lane) * 4 + pp] = perlin_cell(ixf, iyf, fx, fy, u, v, sB,  PH, PM, PL);
                sX[(96 + lane) * 4 + pp] = perlin_cell(ixf, iyf, fx, fy, u, v, sBo, PH, PM, PL);
            }
        }
        __syncwarp();

        // ---- layer 1 (noise part only; z part pre-folded into hz)
        float4 a0 = hz, a1 = hz, a2 = hz, a3 = hz;
        #pragma unroll 4
        for (int cc = 0; cc < 128; ++cc) {
            float4 wv = *reinterpret_cast<const float4*>(sW1 + cc * 128 + lane * 4);
            float4 xq = *reinterpret_cast<const float4*>(sX + cc * 4);
            a0.x = fmaf(wv.x, xq.x, a0.x); a0.y = fmaf(wv.y, xq.x, a0.y);
            a0.z = fmaf(wv.z, xq.x, a0.z); a0.w = fmaf(wv.w, xq.x, a0.w);
            a1.x = fmaf(wv.x, xq.y, a1.x); a1.y = fmaf(wv.y, xq.y, a1.y);
            a1.z = fmaf(wv.z, xq.y, a1.z); a1.w = fmaf(wv.w, xq.y, a1.w);
            a2.x = fmaf(wv.x, xq.z, a2.x); a2.y = fmaf(wv.y, xq.z, a2.y);
            a2.z = fmaf(wv.z, xq.z, a2.z); a2.w = fmaf(wv.w, xq.z, a2.w);
            a3.x = fmaf(wv.x, xq.w, a3.x); a3.y = fmaf(wv.y, xq.w, a3.y);
            a3.z = fmaf(wv.z, xq.w, a3.z); a3.w = fmaf(wv.w, xq.w, a3.w);
        }
        a0.x = fmaxf(a0.x, 0.0f); a0.y = fmaxf(a0.y, 0.0f); a0.z = fmaxf(a0.z, 0.0f); a0.w = fmaxf(a0.w, 0.0f);
        a1.x = fmaxf(a1.x, 0.0f); a1.y = fmaxf(a1.y, 0.0f); a1.z = fmaxf(a1.z, 0.0f); a1.w = fmaxf(a1.w, 0.0f);
        a2.x = fmaxf(a2.x, 0.0f); a2.y = fmaxf(a2.y, 0.0f); a2.z = fmaxf(a2.z, 0.0f); a2.w = fmaxf(a2.w, 0.0f);
        a3.x = fmaxf(a3.x, 0.0f); a3.y = fmaxf(a3.y, 0.0f); a3.z = fmaxf(a3.z, 0.0f); a3.w = fmaxf(a3.w, 0.0f);

        __syncwarp();
        #pragma unroll
        for (int k = 0; k < 4; ++k) {
            reinterpret_cast<float4*>(sX)[4 * lane + k] =
                make_float4(f4get(a0, k), f4get(a1, k), f4get(a2, k), f4get(a3, k));
        }
        __syncwarp();

        // ---- layer 2
        float4 c0 = b2v, c1 = b2v, c2 = b2v, c3 = b2v;
        #pragma unroll 4
        for (int cc = 0; cc < 128; ++cc) {
            float4 wv = *reinterpret_cast<const float4*>(sW2 + cc * 128 + lane * 4);
            float4 xq = *reinterpret_cast<const float4*>(sX + cc * 4);
            c0.x = fmaf(wv.x, xq.x, c0.x); c0.y = fmaf(wv.y, xq.x, c0.y);
            c0.z = fmaf(wv.z, xq.x, c0.z); c0.w = fmaf(wv.w, xq.x, c0.w);
            c1.x = fmaf(wv.x, xq.y, c1.x); c1.y = fmaf(wv.y, xq.y, c1.y);
            c1.z = fmaf(wv.z, xq.y, c1.z); c1.w = fmaf(wv.w, xq.y, c1.w);
            c2.x = fmaf(wv.x, xq.z, c2.x); c2.y = fmaf(wv.y, xq.z, c2.y);
            c2.z = fmaf(wv.z, xq.z, c2.z); c2.w = fmaf(wv.w, xq.z, c2.w);
            c3.x = fmaf(wv.x, xq.w, c3.x); c3.y = fmaf(wv.y, xq.w, c3.y);
            c3.z = fmaf(wv.z, xq.w, c3.z); c3.w = fmaf(wv.w, xq.w, c3.w);
        }
        c0.x = fmaxf(c0.x, 0.0f); c0.y = fmaxf(c0.y, 0.0f); c0.z = fmaxf(c0.z, 0.0f); c0.w = fmaxf(c0.w, 0.0f);
        c1.x = fmaxf(c1.x, 0.0f); c1.y = fmaxf(c1.y, 0.0f); c1.z = fmaxf(c1.z, 0.0f); c1.w = fmaxf(c1.w, 0.0f);
        c2.x = fmaxf(c2.x, 0.0f); c2.y = fmaxf(c2.y, 0.0f); c2.z = fmaxf(c2.z, 0.0f); c2.w = fmaxf(c2.w, 0.0f);
        c3.x = fmaxf(c3.x, 0.0f); c3.y = fmaxf(c3.y, 0.0f); c3.z = fmaxf(c3.z, 0.0f); c3.w = fmaxf(c3.w, 0.0f);

        // ---- layer 3 + tanh + store
        #pragma unroll
        for (int pp = 0; pp < 4; ++pp) {
            float4 h = (pp == 0) ? c0 : (pp == 1) ? c1 : (pp == 2) ? c2 : c3;
            float r0 = fmaf(w30.x, h.x, fmaf(w30.y, h.y, fmaf(w30.z, h.z, w30.w * h.w)));
            float r1 = fmaf(w31.x, h.x, fmaf(w31.y, h.y, fmaf(w31.z, h.z, w31.w * h.w)));
            float r2 = fmaf(w32.x, h.x, fmaf(w32.y, h.y, fmaf(w32.z, h.z, w32.w * h.w)));
            #pragma unroll
            for (int sh = 16; sh > 0; sh >>= 1) {
                r0 += __shfl_xor_sync(0xffffffffu, r0, sh);
                r1 += __shfl_xor_sync(0xffffffffu, r1, sh);
                r2 += __shfl_xor_sync(0xffffffffu, r2, sh);
            }
            if (lane == pp) {
                int pix = base + pp;
                outb[pix]            = tanhf(r0 + b30);
                outb[NPIX + pix]     = tanhf(r1 + b31);
                outb[2 * NPIX + pix] = tanhf(r2 + b32);
            }
        }
    }
}

extern "C" void kernel_launch(void* const* d_in, const int* in_sizes, int n_in,
                              void* d_out, int out_size) {
    const float* position = (const float*)d_in[0];
    const float* seed     = (const float*)d_in[1];
    const float* wb       = (const float*)d_in[2];
    const float* fcw      = (const float*)d_in[3];
    const float* fcb      = (const float*)d_in[4];
    const float* sw       = (const float*)d_in[5];
    const float* sb       = (const float*)d_in[6];
    const float* w1       = (const float*)d_in[7];
    const float* b1       = (const float*)d_in[8];
    const float* w2       = (const float*)d_in[9];
    const float* b2       = (const float*)d_in[10];
    const float* w3       = (const float*)d_in[11];
    const float* b3       = (const float*)d_in[12];
    float* out = (float*)d_out;

    cudaFuncSetAttribute(texgen_main, cudaFuncAttributeMaxDynamicSharedMemorySize, SMEM_BYTES);

    texgen_setup<<<1, 512>>>(wb, fcw, fcb, sw, sb, w1, b1, out);
    texgen_main<<<4 * BPB, THREADS, SMEM_BYTES>>>(position, seed, w1, w2, b2, w3, b3, out);
}

// round 14
// speedup vs baseline: 1.9505x; 1.2187x over previous
#include <cuda_runtime.h>

#define RES 256
#define NPIX 65536
#define BPB 37           // blocks per batch (4*37 = 148 blocks = 1/SM)
#define NWARP 16
#define THREADS 512
#define IMG_OFF 0
#define WB_OFF  786432
#define SUB_OFF 786944
#define SMEM_FLOATS (33092 + NWARP * 512)
#define SMEM_BYTES  (SMEM_FLOATS * 4)

__device__ float g_weights[4 * 68];   // per batch: [0..3]=transform coeff, [4..67]=z
__device__ float g_h1z[4 * 128];      // b1 + W1[:, :64] @ z  (per batch)
__device__ float g_pio2[3];           // exact-split pi/2 triple (ph, pm, pl)

// compile-time ff splits of double coefficients
#define FFH(c) ((float)(c))
#define FFL(c) ((float)((c) - (double)(float)(c)))

// Correctly-rounded-matching f32 sine on the FP32 pipe.
// Cody-Waite reduction (bit-exact, unchanged) + parity-selected Taylor Horner
// in LAZY double-single arithmetic (unnormalized hi/lo pairs; renormalization
// elided). c3 and below evaluated in plain f32 (contributes ~1e-10 abs).
// Total abs error ~1e-10 -> mismatch rate vs glibc ~2e-3 -> image +~2e-4.
__device__ __forceinline__ float sin_cr(float x, float PH, float PM, float PL) {
    float kf = rintf(__fmul_rn(x, 0.63661977236758134f));
    int q = (int)kf;
    // ---- reduction (unchanged, proven) ----
    float t1  = __fmul_rn(kf, PH);
    float t1e = fmaf(kf, PH, -t1);
    float t2  = __fmul_rn(kf, PM);
    float t2e = fmaf(kf, PM, -t2);
    float hi  = __fsub_rn(x, t1);                         // exact (Sterbenz-range)
    float s   = __fsub_rn(hi, t1e);
    float bb  = __fsub_rn(s, hi);
    float err = __fadd_rn(__fsub_rn(hi, __fsub_rn(s, bb)), __fsub_rn(-t1e, bb));
    float s2   = __fsub_rn(s, t2);
    float bb2  = __fsub_rn(s2, s);
    float err2 = __fadd_rn(__fsub_rn(s, __fsub_rn(s2, bb2)), __fsub_rn(-t2, bb2));
    float lo = __fsub_rn(__fadd_rn(err, err2), __fadd_rn(t2e, __fmul_rn(kf, PL)));
    float rh = __fadd_rn(s2, lo);
    float rl = __fsub_rn(lo, __fsub_rn(rh, s2));

    // ---- r^2 as lazy pair ----
    float r2h = __fmul_rn(rh, rh);
    float r2l = fmaf(rh, rh, -r2h);
    r2l = fmaf(__fadd_rn(rh, rh), rl, r2l);
    float r2f = r2h;

    const bool odd = (q & 1);
    float c1h = odd ? FFH(-1.0/2.0)   : FFH(-1.0/6.0);
    float c1l = odd ? FFL(-1.0/2.0)   : FFL(-1.0/6.0);
    float c2h = odd ? FFH(1.0/24.0)   : FFH(1.0/120.0);
    float c2l = odd ? FFL(1.0/24.0)   : FFL(1.0/120.0);
    float a3 = odd ? (float)(-1.0/720.0)         : (float)(-1.0/5040.0);
    float a4 = odd ? (float)(1.0/40320.0)        : (float)(1.0/362880.0);
    float a5 = odd ? (float)(-1.0/3628800.0)     : (float)(-1.0/39916800.0);
    float a6 = odd ? (float)(1.0/479001600.0)    : (float)(1.0/6227020800.0);

    // f32 tail: c3 + r2*(a4 + r2*(a5 + r2*a6))
    float T = fmaf(r2f, fmaf(r2f, fmaf(r2f, a6, a5), a4), a3);

    // level c2 (lazy ff):  acc = c2 + r2*T
    float ph_ = __fmul_rn(r2h, T);
    float pl_ = fmaf(r2h, T, -ph_);
    pl_ = fmaf(r2l, T, pl_);
    float sh = __fadd_rn(c2h, ph_);
    float sl = __fadd_rn(__fsub_rn(ph_, __fsub_rn(sh, c2h)), __fadd_rn(c2l, pl_));

    // level c1:  acc = c1 + r2*acc
    ph_ = __fmul_rn(r2h, sh);
    pl_ = fmaf(r2h, sh, -ph_);
    pl_ = fmaf(r2h, sl, pl_);
    pl_ = fmaf(r2l, sh, pl_);
    float sh2 = __fadd_rn(c1h, ph_);
    float sl2 = __fadd_rn(__fsub_rn(ph_, __fsub_rn(sh2, c1h)), __fadd_rn(c1l, pl_));

    // level 1:   acc = 1 + r2*acc
    ph_ = __fmul_rn(r2h, sh2);
    pl_ = fmaf(r2h, sh2, -ph_);
    pl_ = fmaf(r2h, sl2, pl_);
    pl_ = fmaf(r2l, sh2, pl_);
    float sh3 = __fadd_rn(1.0f, ph_);
    float sl3 = __fadd_rn(__fsub_rn(ph_, __fsub_rn(sh3, 1.0f)), pl_);

    // final: res = m * acc, m = r (even: sin) or 1 (odd: cos)
    float mh = odd ? 1.0f : rh;
    float ml = odd ? 0.0f : rl;
    float p = __fmul_rn(mh, sh3);
    float e = fmaf(mh, sh3, -p);
    e = fmaf(mh, sl3, e);
    e = fmaf(ml, sh3, e);
    float res = __fadd_rn(p, e);
    return (q & 2) ? -res : res;
}

// Fade: only feeds smooth interpolation -> rounding non-critical.
__device__ __forceinline__ float fadef(float t) {
    float t2 = t * t;
    return t2 * t * fmaf(t, fmaf(t, 6.0f, -15.0f), 10.0f);
}

// hash -> unit gradient -> dot with corner offset.
__device__ __forceinline__ float grad_dot(float cix, float ciy, float s, float ox, float oy,
                                          float PH, float PM, float PL) {
    float arg = __fadd_rn(__fadd_rn(__fmul_rn(cix, 127.1f), __fmul_rn(ciy, 311.7f)),
                          __fmul_rn(s, 74.7f));
    float h   = __fmul_rn(sin_cr(arg, PH, PM, PL), 43758.5453f);
    float fr  = __fsub_rn(h, floorf(h));
    float ang = __fmul_rn(fr, 6.2831853071795862f);
    float gx, gy;
    __sincosf(ang, &gy, &gx);
    return __fadd_rn(__fmul_rn(gx, ox), __fmul_rn(gy, oy));
}

__device__ __forceinline__ float perlin_cell(float ix, float iy, float fx, float fy,
                                             float u, float v, float s,
                                             float PH, float PM, float PL) {
    float n00 = grad_dot(ix,        iy,        s, fx,        fy,        PH, PM, PL);
    float n10 = grad_dot(ix + 1.0f, iy,        s, fx - 1.0f, fy,        PH, PM, PL);
    float n01 = grad_dot(ix,        iy + 1.0f, s, fx,        fy - 1.0f, PH, PM, PL);
    float n11 = grad_dot(ix + 1.0f, iy + 1.0f, s, fx - 1.0f, fy - 1.0f, PH, PM, PL);
    float nx0 = fmaf(u, n10 - n00, n00);
    float nx1 = fmaf(u, n11 - n01, n01);
    return fmaf(v, nx1 - nx0, nx0);
}

__device__ __forceinline__ float f4get(const float4& v, int k) {
    return k == 0 ? v.x : (k == 1 ? v.y : (k == 2 ? v.z : v.w));
}

// ---------------------------------------------------------------------------
// Setup: bottleneck GEMMs in f64 (one-time), z-folded layer-1 partial, pi/2.
// ---------------------------------------------------------------------------
__global__ void __launch_bounds__(512)
texgen_setup(const float* __restrict__ wb,  const float* __restrict__ fcw,
             const float* __restrict__ fcb, const float* __restrict__ sw,
             const float* __restrict__ sb,  const float* __restrict__ w1,
             const float* __restrict__ b1,  float* __restrict__ out)
{
    __shared__ float sWb[512];
    const int tid = threadIdx.x;
    sWb[tid] = wb[tid];
    out[WB_OFF + tid] = wb[tid];            // pass-through output (exact copy)
    if (tid == 0) {
        const double PIO2_HI = 1.5707963267948966;
        const double PIO2_LO = 6.123233995736766e-17;
        float ph = (float)PIO2_HI;
        float pm = (float)(PIO2_HI - (double)ph);
        double rem = (PIO2_HI - (double)ph - (double)pm) + PIO2_LO;
        g_pio2[0] = ph; g_pio2[1] = pm; g_pio2[2] = (float)rem;
    }
    __syncthreads();

    for (int i = tid; i < 4 * 68; i += 512) {
        int b = i / 68, j = i % 68;
        double acc = 0.0;
        const float* wr = fcw + j * 128;
        const float* br = sWb + b * 128;
        #pragma unroll 8
        for (int k = 0; k < 128; ++k) acc = fma((double)br[k], (double)wr[k], acc);
        g_weights[i] = (float)(acc + (double)fcb[j]);
    }
    if (tid < 16) {
        int b = tid / 4, j = tid % 4;
        double acc = 0.0;
        #pragma unroll 8
        for (int k = 0; k < 128; ++k)
            acc = fma((double)sWb[b * 128 + k], (double)sw[j * 128 + k], acc);
        out[SUB_OFF + tid] = (float)(acc + (double)sb[j]);
    }
    __syncthreads();

    {
        int b = tid >> 7, j = tid & 127;
        double acc = 0.0;
        const float* zr = g_weights + b * 68 + 4;
        const float* wr = w1 + j * 192;
        #pragma unroll 8
        for (int k = 0; k < 64; ++k) acc = fma((double)zr[k], (double)wr[k], acc);
        g_h1z[tid] = (float)(acc + (double)b1[j]);
    }
}

// ---------------------------------------------------------------------------
// Main: per-warp, 4 pixels/iteration. Noise -> SMEM x -> 2 GEMV layers with
// SMEM-resident transposed weights -> warp-reduced 3-ch output + tanh.
// ---------------------------------------------------------------------------
__global__ void __launch_bounds__(THREADS, 1)
texgen_main(const float* __restrict__ position,
            const float* __restrict__ seed,
            const float* __restrict__ dec_w1,
            const float* __restrict__ dec_w2,
            const float* __restrict__ dec_b2,
            const float* __restrict__ dec_w3,
            const float* __restrict__ dec_b3,
            float* __restrict__ out)
{
    extern __shared__ float sm[];
    float* sW1   = sm;            // [128 noise-ch][128 j]  (transposed)
    float* sW2   = sm + 16384;    // [128 c][128 j]
    float* sB2   = sm + 32768;    // [128]
    float* sHz   = sm + 32896;    // [128]
    float* sSeed = sm + 33024;    // [64]
    float* sTc   = sm + 33088;    // [4]

    const int tid   = threadIdx.x;
    const int batch = blockIdx.x / BPB;
    const int bb    = blockIdx.x % BPB;

    for (int i = tid; i < 16384; i += THREADS) {
        int cc = i >> 7, j = i & 127;
        sW1[i] = dec_w1[j * 192 + 64 + cc];
        sW2[i] = dec_w2[j * 128 + cc];
    }
    if (tid < 128) { sB2[tid] = dec_b2[tid]; sHz[tid] = g_h1z[batch * 128 + tid]; }
    if (tid < 64)  sSeed[tid] = seed[batch * 64 + tid];
    if (tid < 4)   sTc[tid]   = g_weights[batch * 68 + tid];
    __syncthreads();

    const float PH = g_pio2[0], PM = g_pio2[1], PL = g_pio2[2];

    const int lane = tid & 31;
    const int warp = tid >> 5;
    const int o1   = lane >> 3;      // octave A for this lane (0..3)
    const int ch   = lane & 7;       // noise channel

    const float sA   = sSeed[o1 * 8 + ch];
    const float sB   = sSeed[(o1 + 4) * 8 + ch];
    const float sA2  = __fadd_rn(sA, 17.1312f);   // SEED_OFFSET, f32 add
    const float sBo  = __fadd_rn(sB, 17.1312f);
    const float sclA = (float)(1 << o1);
    const float sclB = sclA * 16.0f;
    const float tc0 = sTc[0], tc1 = sTc[1], tc2 = sTc[2], tc3 = sTc[3];
    const float4 hz  = *reinterpret_cast<const float4*>(sHz + 4 * lane);
    const float4 b2v = *reinterpret_cast<const float4*>(sB2 + 4 * lane);
    const float4 w30 = reinterpret_cast<const float4*>(dec_w3)[lane];
    const float4 w31 = reinterpret_cast<const float4*>(dec_w3 + 128)[lane];
    const float4 w32 = reinterpret_cast<const float4*>(dec_w3 + 256)[lane];
    const float b30 = dec_b3[0], b31 = dec_b3[1], b32 = dec_b3[2];

    float* sX = sm + 33092 + warp * 512;     // [128 ch][4 pixels]
    const float* posb = position + batch * (2 * NPIX);
    float* outb = out + IMG_OFF + batch * (3 * NPIX);

    const int gw     = bb * NWARP + warp;
    const int stride = BPB * NWARP * 4;

    for (int base = gw * 4; base < NPIX; base += stride) {
        __syncwarp();
        // ---- noise: each lane computes 4 channels (2 octaves x 2 seed variants)
        for (int pp = 0; pp < 4; ++pp) {
            int pix = base + pp;
            float px = posb[pix];
            float py = posb[NPIX + pix];
            float xp = __fadd_rn(__fmul_rn(px, tc0), __fmul_rn(py, tc2));
            float yp = __fadd_rn(__fmul_rn(px, tc1), __fmul_rn(py, tc3));
            {   // octave A
                float pxo = __fmul_rn(xp, sclA), pyo = __fmul_rn(yp, sclA);
                float ixf = floorf(pxo), iyf = floorf(pyo);
                float fx = __fsub_rn(pxo, ixf), fy = __fsub_rn(pyo, iyf);
                float u = fadef(fx), v = fadef(fy);
                sX[lane * 4 + pp]        = perlin_cell(ixf, iyf, fx, fy, u, v, sA,  PH, PM, PL);
                sX[(64 + lane) * 4 + pp] = perlin_cell(ixf, iyf, fx, fy, u, v, sA2, PH, PM, PL);
            }
            {   // octave B
                float pxo = __fmul_rn(xp, sclB), pyo = __fmul_rn(yp, sclB);
                float ixf = floorf(pxo), iyf = floorf(pyo);
                float fx = __fsub_rn(pxo, ixf), fy = __fsub_rn(pyo, iyf);
                float u = fadef(fx), v = fadef(fy);
                sX[(32 + lane) * 4 + pp] = perlin_cell(ixf, iyf, fx, fy, u, v, sB,  PH, PM, PL);
                sX[(96 + lane) * 4 + pp] = perlin_cell(ixf, iyf, fx, fy, u, v, sBo, PH, PM, PL);
            }
        }
        __syncwarp();

        // ---- layer 1 (noise part only; z part pre-folded into hz)
        float4 a0 = hz, a1 = hz, a2 = hz, a3 = hz;
        #pragma unroll 4
        for (int cc = 0; cc < 128; ++cc) {
            float4 wv = *reinterpret_cast<const float4*>(sW1 + cc * 128 + lane * 4);
            float4 xq = *reinterpret_cast<const float4*>(sX + cc * 4);
            a0.x = fmaf(wv.x, xq.x, a0.x); a0.y = fmaf(wv.y, xq.x, a0.y);
            a0.z = fmaf(wv.z, xq.x, a0.z); a0.w = fmaf(wv.w, xq.x, a0.w);
            a1.x = fmaf(wv.x, xq.y, a1.x); a1.y = fmaf(wv.y, xq.y, a1.y);
            a1.z = fmaf(wv.z, xq.y, a1.z); a1.w = fmaf(wv.w, xq.y, a1.w);
            a2.x = fmaf(wv.x, xq.z, a2.x); a2.y = fmaf(wv.y, xq.z, a2.y);
            a2.z = fmaf(wv.z, xq.z, a2.z); a2.w = fmaf(wv.w, xq.z, a2.w);
            a3.x = fmaf(wv.x, xq.w, a3.x); a3.y = fmaf(wv.y, xq.w, a3.y);
            a3.z = fmaf(wv.z, xq.w, a3.z); a3.w = fmaf(wv.w, xq.w, a3.w);
        }
        a0.x = fmaxf(a0.x, 0.0f); a0.y = fmaxf(a0.y, 0.0f); a0.z = fmaxf(a0.z, 0.0f); a0.w = fmaxf(a0.w, 0.0f);
        a1.x = fmaxf(a1.x, 0.0f); a1.y = fmaxf(a1.y, 0.0f); a1.z = fmaxf(a1.z, 0.0f); a1.w = fmaxf(a1.w, 0.0f);
        a2.x = fmaxf(a2.x, 0.0f); a2.y = fmaxf(a2.y, 0.0f); a2.z = fmaxf(a2.z, 0.0f); a2.w = fmaxf(a2.w, 0.0f);
        a3.x = fmaxf(a3.x, 0.0f); a3.y = fmaxf(a3.y, 0.0f); a3.z = fmaxf(a3.z, 0.0f); a3.w = fmaxf(a3.w, 0.0f);

        __syncwarp();
        #pragma unroll
        for (int k = 0; k < 4; ++k) {
            reinterpret_cast<float4*>(sX)[4 * lane + k] =
                make_float4(f4get(a0, k), f4get(a1, k), f4get(a2, k), f4get(a3, k));
        }
        __syncwarp();

        // ---- layer 2
        float4 c0 = b2v, c1 = b2v, c2 = b2v, c3 = b2v;
        #pragma unroll 4
        for (int cc = 0; cc < 128; ++cc) {
            float4 wv = *reinterpret_cast<const float4*>(sW2 + cc * 128 + lane * 4);
            float4 xq = *reinterpret_cast<const float4*>(sX + cc * 4);
            c0.x = fmaf(wv.x, xq.x, c0.x); c0.y = fmaf(wv.y, xq.x, c0.y);
            c0.z = fmaf(wv.z, xq.x, c0.z); c0.w = fmaf(wv.w, xq.x, c0.w);
            c1.x = fmaf(wv.x, xq.y, c1.x); c1.y = fmaf(wv.y, xq.y, c1.y);
            c1.z = fmaf(wv.z, xq.y, c1.z); c1.w = fmaf(wv.w, xq.y, c1.w);
            c2.x = fmaf(wv.x, xq.z, c2.x); c2.y = fmaf(wv.y, xq.z, c2.y);
            c2.z = fmaf(wv.z, xq.z, c2.z); c2.w = fmaf(wv.w, xq.z, c2.w);
            c3.x = fmaf(wv.x, xq.w, c3.x); c3.y = fmaf(wv.y, xq.w, c3.y);
            c3.z = fmaf(wv.z, xq.w, c3.z); c3.w = fmaf(wv.w, xq.w, c3.w);
        }
        c0.x = fmaxf(c0.x, 0.0f); c0.y = fmaxf(c0.y, 0.0f); c0.z = fmaxf(c0.z, 0.0f); c0.w = fmaxf(c0.w, 0.0f);
        c1.x = fmaxf(c1.x, 0.0f); c1.y = fmaxf(c1.y, 0.0f); c1.z = fmaxf(c1.z, 0.0f); c1.w = fmaxf(c1.w, 0.0f);
        c2.x = fmaxf(c2.x, 0.0f); c2.y = fmaxf(c2.y, 0.0f); c2.z = fmaxf(c2.z, 0.0f); c2.w = fmaxf(c2.w, 0.0f);
        c3.x = fmaxf(c3.x, 0.0f); c3.y = fmaxf(c3.y, 0.0f); c3.z = fmaxf(c3.z, 0.0f); c3.w = fmaxf(c3.w, 0.0f);

        // ---- layer 3 + tanh + store
        #pragma unroll
        for (int pp = 0; pp < 4; ++pp) {
            float4 h = (pp == 0) ? c0 : (pp == 1) ? c1 : (pp == 2) ? c2 : c3;
            float r0 = fmaf(w30.x, h.x, fmaf(w30.y, h.y, fmaf(w30.z, h.z, w30.w * h.w)));
            float r1 = fmaf(w31.x, h.x, fmaf(w31.y, h.y, fmaf(w31.z, h.z, w31.w * h.w)));
            float r2 = fmaf(w32.x, h.x, fmaf(w32.y, h.y, fmaf(w32.z, h.z, w32.w * h.w)));
            #pragma unroll
            for (int sh = 16; sh > 0; sh >>= 1) {
                r0 += __shfl_xor_sync(0xffffffffu, r0, sh);
                r1 += __shfl_xor_sync(0xffffffffu, r1, sh);
                r2 += __shfl_xor_sync(0xffffffffu, r2, sh);
            }
            if (lane == pp) {
                int pix = base + pp;
                outb[pix]            = tanhf(r0 + b30);
                outb[NPIX + pix]     = tanhf(r1 + b31);
                outb[2 * NPIX + pix] = tanhf(r2 + b32);
            }
        }
    }
}

extern "C" void kernel_launch(void* const* d_in, const int* in_sizes, int n_in,
                              void* d_out, int out_size) {
    const float* position = (const float*)d_in[0];
    const float* seed     = (const float*)d_in[1];
    const float* wb       = (const float*)d_in[2];
    const float* fcw      = (const float*)d_in[3];
    const float* fcb      = (const float*)d_in[4];
    const float* sw       = (const float*)d_in[5];
    const float* sb       = (const float*)d_in[6];
    const float* w1       = (const float*)d_in[7];
    const float* b1       = (const float*)d_in[8];
    const float* w2       = (const float*)d_in[9];
    const float* b2       = (const float*)d_in[10];
    const float* w3       = (const float*)d_in[11];
    const float* b3       = (const float*)d_in[12];
    float* out = (float*)d_out;

    cudaFuncSetAttribute(texgen_main, cudaFuncAttributeMaxDynamicSharedMemorySize, SMEM_BYTES);

    texgen_setup<<<1, 512>>>(wb, fcw, fcb, sw, sb, w1, b1, out);
    texgen_main<<<4 * BPB, THREADS, SMEM_BYTES>>>(position, seed, w1, w2, b2, w3, b3, out);
}